// round 6
// baseline (speedup 1.0000x reference)
#include <cuda_runtime.h>
#include <cuda_fp16.h>
#include <cfloat>

#define BB 4
#define CC 64
#define NN 65536
#define KK 16
#define TILE_N 64

// 33.5 MB transposed fp16 features: [B][N][C]
__device__ __align__(16) __half g_ft[(size_t)BB * NN * CC];

// ---------------------------------------------------------------------------
// Kernel 1: transpose + convert: features [B][C][N] f32 -> g_ft [B][N][C] f16
// 64x64 tile, 256 threads. Row pad 68 floats (272B = 16B-aligned float4 rows).
// ---------------------------------------------------------------------------
__global__ __launch_bounds__(256) void transpose_kernel(const float* __restrict__ f) {
    __shared__ float tile[64][68];
    int b  = blockIdx.z;
    int n0 = blockIdx.x * 64;
    int tid = threadIdx.x;

    // Load: 64 rows (c) x 16 float4 (n). rx = n-quad, ry = base row.
    int rx = tid & 15;
    int ry = tid >> 4;
    const float4* src = (const float4*)(f + (size_t)b * CC * NN + n0);
#pragma unroll
    for (int j = 0; j < 4; j++) {
        int c = ry + 16 * j;
        float4 v = __ldcs(&src[(size_t)c * (NN / 4) + rx]);
        *(float4*)&tile[c][rx * 4] = v;   // 272B row stride: aligned
    }
    __syncthreads();

    // Store: 64 rows (n) x 8 uint4 (8 halves = 8 channels each).
    // Channel reads rotated by tx -> all 32 lanes hit distinct banks.
    int tx = tid & 7;    // channel octet
    int ty = tid >> 3;   // 0..31, base n row
    __half* dst = g_ft + ((size_t)b * NN + n0) * CC;
#pragma unroll
    for (int j = 0; j < 2; j++) {
        int n = ty + 32 * j;
        int c = tx * 8;
        union { uint4 v; __half hh[8]; } u;
#pragma unroll
        for (int dt = 0; dt < 8; dt++) {
            int ch = (dt + tx) & 7;                    // rotated read order
            u.hh[ch] = __float2half_rn(tile[c + ch][n]);
        }
        *(uint4*)&dst[(size_t)n * CC + c] = u.v;
    }
}

// ---------------------------------------------------------------------------
// Kernel 2: gather + max in fp16.
// Block = 256 threads (8 warps), one batch b, TILE_N=64 columns.
// Quarter-warp (8 lanes x uint4 = 64 halves) covers one 128B feature row.
// Warp handles 8 columns: 4 per quarter-warp slot x 2 interleaved streams.
// ---------------------------------------------------------------------------
__global__ __launch_bounds__(256) void gather_max_kernel(
    const int* __restrict__ nb, float* __restrict__ out)
{
    __shared__ int   s_idx[KK][TILE_N];
    __shared__ float s_out[CC][TILE_N + 1];

    int b  = blockIdx.y;
    int n0 = blockIdx.x * TILE_N;
    int tid = threadIdx.x;

    // Phase 1: stage index tile (coalesced along n)
    const int* nbp = nb + (size_t)b * KK * NN + n0;
    for (int i = tid; i < KK * TILE_N; i += 256) {
        int k = i >> 6;
        int j = i & (TILE_N - 1);
        s_idx[k][j] = nbp[(size_t)k * NN + j];
    }
    __syncthreads();

    // Phase 2: gather-max, two independent column streams per warp
    int warp = tid >> 5;
    int lane = tid & 31;
    int q    = lane >> 3;   // quarter-warp: column slot 0..3
    int cg   = lane & 7;    // channel octet: channels [8*cg, 8*cg+7]

    const uint4* ftb = (const uint4*)(g_ft + (size_t)b * NN * CC);

    int colA = warp * 8 + q;
    int colB = colA + 4;

    const __half2 ninf2 = __halves2half2(__ushort_as_half(0xFC00),
                                         __ushort_as_half(0xFC00));
    __half2 accA[4] = {ninf2, ninf2, ninf2, ninf2};
    __half2 accB[4] = {ninf2, ninf2, ninf2, ninf2};

#pragma unroll
    for (int k = 0; k < KK; k++) {
        int idxA = s_idx[k][colA];
        int idxB = s_idx[k][colB];
        uint4 ra = __ldg(&ftb[(size_t)idxA * (CC / 8) + cg]);
        uint4 rb = __ldg(&ftb[(size_t)idxB * (CC / 8) + cg]);
        const __half2* va = (const __half2*)&ra;
        const __half2* vb = (const __half2*)&rb;
#pragma unroll
        for (int t = 0; t < 4; t++) {
            accA[t] = __hmax2(accA[t], va[t]);
            accB[t] = __hmax2(accB[t], vb[t]);
        }
    }

    int c = cg * 8;
#pragma unroll
    for (int t = 0; t < 4; t++) {
        float2 fa = __half22float2(accA[t]);
        float2 fb = __half22float2(accB[t]);
        s_out[c + 2 * t + 0][colA] = fa.x;
        s_out[c + 2 * t + 1][colA] = fa.y;
        s_out[c + 2 * t + 0][colB] = fb.x;
        s_out[c + 2 * t + 1][colB] = fb.y;
    }
    __syncthreads();

    // Phase 3: coalesced streaming output write [B][C][N]
    float* outp = out + (size_t)b * CC * NN + n0;
    for (int i = tid; i < CC * TILE_N; i += 256) {
        int cc = i >> 6;
        int j  = i & 63;
        __stcs(&outp[(size_t)cc * NN + j], s_out[cc][j]);
    }
}

extern "C" void kernel_launch(void* const* d_in, const int* in_sizes, int n_in,
                              void* d_out, int out_size)
{
    const float* features     = (const float*)d_in[0];
    const int*   neighborhood = (const int*)d_in[1];
    float*       out          = (float*)d_out;

    dim3 tgrid(NN / 64, 1, BB);   // (1024, 1, 4)
    transpose_kernel<<<tgrid, 256>>>(features);

    dim3 ggrid(NN / TILE_N, BB);  // (1024, 4)
    gather_max_kernel<<<ggrid, 256>>>(neighborhood, out);
}

// round 8
// speedup vs baseline: 2.0403x; 2.0403x over previous
#include <cuda_runtime.h>
#include <cuda_fp16.h>
#include <cfloat>

#define BB 4
#define CC 64
#define NN 65536
#define KK 16
#define TILE_N 64

// 33.5 MB transposed fp16 features: [B][N][C]
__device__ __align__(16) __half g_ft[(size_t)BB * NN * CC];

// ---------------------------------------------------------------------------
// Kernel 1: transpose + convert: features [B][C][N] f32 -> g_ft [B][N][C] f16
// 64x64 tile, 256 threads. Row pad 68 floats (272B: float4 rows 16B-aligned).
// Conversions use PACKED __floats2half2_rn (fast F2FP pipe) — scalar
// __float2half_rn runs on the quarter-rate convert pipe and cost ~55us in R6.
// ---------------------------------------------------------------------------
__global__ __launch_bounds__(256) void transpose_kernel(const float* __restrict__ f) {
    __shared__ float tile[64][68];
    int b  = blockIdx.z;
    int n0 = blockIdx.x * 64;
    int tid = threadIdx.x;

    // Load: 64 rows (c) x 16 float4 (n). rx = n-quad, ry = base row.
    int rx = tid & 15;
    int ry = tid >> 4;
    const float4* src = (const float4*)(f + (size_t)b * CC * NN + n0);
#pragma unroll
    for (int j = 0; j < 4; j++) {
        int c = ry + 16 * j;
        float4 v = __ldcs(&src[(size_t)c * (NN / 4) + rx]);
        *(float4*)&tile[c][rx * 4] = v;   // 272B row stride: aligned
    }
    __syncthreads();

    // Store: 64 rows (n) x 8 uint4 (8 halves = 8 channels each).
    // Pair-rotated reads: p=(t+tx)&3 -> at worst 2-way LDS conflicts.
    int tx = tid & 7;    // channel octet
    int ty = tid >> 3;   // 0..31, base n row
    __half* dst = g_ft + ((size_t)b * NN + n0) * CC;
#pragma unroll
    for (int j = 0; j < 2; j++) {
        int n = ty + 32 * j;
        int c = tx * 8;
        uint4 hv;                       // 16B-aligned storage
        __half2* h = (__half2*)&hv;
#pragma unroll
        for (int t = 0; t < 4; t++) {
            int p = (t + tx) & 3;       // rotated pair index
            h[p] = __floats2half2_rn(tile[c + 2 * p][n], tile[c + 2 * p + 1][n]);
        }
        *(uint4*)&dst[(size_t)n * CC + c] = hv;
    }
}

// ---------------------------------------------------------------------------
// Kernel 2: gather + max in fp16. (unchanged from R6 — measured 46.3us)
// Block = 256 threads (8 warps), one batch b, TILE_N=64 columns.
// Quarter-warp (8 lanes x uint4 = 64 halves) covers one 128B feature row.
// ---------------------------------------------------------------------------
__global__ __launch_bounds__(256) void gather_max_kernel(
    const int* __restrict__ nb, float* __restrict__ out)
{
    __shared__ int   s_idx[KK][TILE_N];
    __shared__ float s_out[CC][TILE_N + 1];

    int b  = blockIdx.y;
    int n0 = blockIdx.x * TILE_N;
    int tid = threadIdx.x;

    // Phase 1: stage index tile (coalesced along n)
    const int* nbp = nb + (size_t)b * KK * NN + n0;
    for (int i = tid; i < KK * TILE_N; i += 256) {
        int k = i >> 6;
        int j = i & (TILE_N - 1);
        s_idx[k][j] = nbp[(size_t)k * NN + j];
    }
    __syncthreads();

    // Phase 2: gather-max, two independent column streams per warp
    int warp = tid >> 5;
    int lane = tid & 31;
    int q    = lane >> 3;   // quarter-warp: column slot 0..3
    int cg   = lane & 7;    // channel octet: channels [8*cg, 8*cg+7]

    const uint4* ftb = (const uint4*)(g_ft + (size_t)b * NN * CC);

    int colA = warp * 8 + q;
    int colB = colA + 4;

    const __half2 ninf2 = __halves2half2(__ushort_as_half(0xFC00),
                                         __ushort_as_half(0xFC00));
    __half2 accA[4] = {ninf2, ninf2, ninf2, ninf2};
    __half2 accB[4] = {ninf2, ninf2, ninf2, ninf2};

#pragma unroll
    for (int k = 0; k < KK; k++) {
        int idxA = s_idx[k][colA];
        int idxB = s_idx[k][colB];
        uint4 ra = __ldg(&ftb[(size_t)idxA * (CC / 8) + cg]);
        uint4 rb = __ldg(&ftb[(size_t)idxB * (CC / 8) + cg]);
        const __half2* va = (const __half2*)&ra;
        const __half2* vb = (const __half2*)&rb;
#pragma unroll
        for (int t = 0; t < 4; t++) {
            accA[t] = __hmax2(accA[t], va[t]);
            accB[t] = __hmax2(accB[t], vb[t]);
        }
    }

    int c = cg * 8;
#pragma unroll
    for (int t = 0; t < 4; t++) {
        float2 fa = __half22float2(accA[t]);
        float2 fb = __half22float2(accB[t]);
        s_out[c + 2 * t + 0][colA] = fa.x;
        s_out[c + 2 * t + 1][colA] = fa.y;
        s_out[c + 2 * t + 0][colB] = fb.x;
        s_out[c + 2 * t + 1][colB] = fb.y;
    }
    __syncthreads();

    // Phase 3: coalesced streaming output write [B][C][N]
    float* outp = out + (size_t)b * CC * NN + n0;
    for (int i = tid; i < CC * TILE_N; i += 256) {
        int cc = i >> 6;
        int j  = i & 63;
        __stcs(&outp[(size_t)cc * NN + j], s_out[cc][j]);
    }
}

extern "C" void kernel_launch(void* const* d_in, const int* in_sizes, int n_in,
                              void* d_out, int out_size)
{
    const float* features     = (const float*)d_in[0];
    const int*   neighborhood = (const int*)d_in[1];
    float*       out          = (float*)d_out;

    dim3 tgrid(NN / 64, 1, BB);   // (1024, 1, 4)
    transpose_kernel<<<tgrid, 256>>>(features);

    dim3 ggrid(NN / TILE_N, BB);  // (1024, 4)
    gather_max_kernel<<<ggrid, 256>>>(neighborhood, out);
}